// round 3
// baseline (speedup 1.0000x reference)
#include <cuda_runtime.h>
#include <math.h>

#define B_ 8
#define T_ 2048
#define D_ 128
#define H_ 4
#define HD_ 32
#define NTOK (B_*T_)
#define SCALE_ 0.17677669529663687f
#define EPS_ 1e-5f
#define LAMBDA_INIT_ 0.8f

// ---------------- scratch (device globals; no allocation allowed) ----------------
__device__ float g_xln[NTOK * D_];              // 8 MB
__device__ float g_q[B_ * H_ * T_ * 64];        // 16 MB  [B,H,T,64]
__device__ float g_k[B_ * H_ * T_ * 64];        // 16 MB
__device__ float g_v[B_ * H_ * T_ * 64];        // 16 MB
__device__ float g_attn[NTOK * 256];            // 16 MB  [B,T, H*64]

// ---------------- kernel 1: LayerNorm ----------------
__global__ __launch_bounds__(256) void ln_kernel(const float* __restrict__ tokens,
                                                 const float* __restrict__ w,
                                                 const float* __restrict__ b) {
    int warp = threadIdx.x >> 5, lane = threadIdx.x & 31;
    int t = blockIdx.x * 8 + warp;
    const float4* src = (const float4*)(tokens + (size_t)t * 128);
    float4 x = src[lane];
    float s = x.x + x.y + x.z + x.w;
    float q = x.x * x.x + x.y * x.y + x.z * x.z + x.w * x.w;
    #pragma unroll
    for (int o = 16; o; o >>= 1) {
        s += __shfl_xor_sync(0xFFFFFFFFu, s, o);
        q += __shfl_xor_sync(0xFFFFFFFFu, q, o);
    }
    float mu = s * (1.f / 128.f);
    float var = q * (1.f / 128.f) - mu * mu;
    float rstd = rsqrtf(var + EPS_);
    float4 wv = ((const float4*)w)[lane];
    float4 bv = ((const float4*)b)[lane];
    float4 y;
    y.x = (x.x - mu) * rstd * wv.x + bv.x;
    y.y = (x.y - mu) * rstd * wv.y + bv.y;
    y.z = (x.z - mu) * rstd * wv.z + bv.z;
    y.w = (x.w - mu) * rstd * wv.w + bv.w;
    ((float4*)g_xln)[(size_t)t * 32 + lane] = y;
}

// ---------------- kernel 2: QKV projection GEMM ----------------
// C[16384 x 768] = X[16384 x 128] @ [wq|wk|wv], scattered to g_q/g_k/g_v [B,H,T,64]
__global__ __launch_bounds__(256) void qkv_gemm_kernel(const float* __restrict__ wq,
                                                       const float* __restrict__ wk,
                                                       const float* __restrict__ wv) {
    __shared__ float sA[64][33];
    __shared__ float sB[32][64];
    int bx = blockIdx.x;            // 0..11 -> 64 output cols each
    int by = blockIdx.y;            // 0..255 -> 64 tokens each
    int seg = bx >> 2;              // 0=q,1=k,2=v
    const float* W = (seg == 0) ? wq : (seg == 1 ? wk : wv);
    int lc0 = (bx & 3) * 64;        // column offset inside 256-wide matrix
    int tid = threadIdx.x;
    int ty = tid >> 4, tx = tid & 15;
    int r0 = ty * 4, c0 = tx * 4;
    float acc[4][4] = {};
    const float* Xb = g_xln + (size_t)(by * 64) * 128;

    for (int kt = 0; kt < 4; kt++) {
        #pragma unroll
        for (int u = 0; u < 2; u++) {
            int f = tid + u * 256;          // 0..511
            int row = f >> 3, c4 = f & 7;
            float4 v = *(const float4*)(Xb + row * 128 + kt * 32 + c4 * 4);
            sA[row][c4 * 4 + 0] = v.x; sA[row][c4 * 4 + 1] = v.y;
            sA[row][c4 * 4 + 2] = v.z; sA[row][c4 * 4 + 3] = v.w;
        }
        #pragma unroll
        for (int u = 0; u < 2; u++) {
            int f = tid + u * 256;
            int kr = f >> 4, c4 = f & 15;
            *(float4*)(&sB[kr][c4 * 4]) =
                *(const float4*)(W + (size_t)(kt * 32 + kr) * 256 + lc0 + c4 * 4);
        }
        __syncthreads();
        #pragma unroll 8
        for (int kk = 0; kk < 32; kk++) {
            float a0 = sA[r0 + 0][kk], a1 = sA[r0 + 1][kk];
            float a2 = sA[r0 + 2][kk], a3 = sA[r0 + 3][kk];
            float4 bvv = *(const float4*)(&sB[kk][c0]);
            acc[0][0] += a0 * bvv.x; acc[0][1] += a0 * bvv.y; acc[0][2] += a0 * bvv.z; acc[0][3] += a0 * bvv.w;
            acc[1][0] += a1 * bvv.x; acc[1][1] += a1 * bvv.y; acc[1][2] += a1 * bvv.z; acc[1][3] += a1 * bvv.w;
            acc[2][0] += a2 * bvv.x; acc[2][1] += a2 * bvv.y; acc[2][2] += a2 * bvv.z; acc[2][3] += a2 * bvv.w;
            acc[3][0] += a3 * bvv.x; acc[3][1] += a3 * bvv.y; acc[3][2] += a3 * bvv.z; acc[3][3] += a3 * bvv.w;
        }
        __syncthreads();
    }
    float* dst = (seg == 0) ? g_q : (seg == 1 ? g_k : g_v);
    int h = bx & 3;
    #pragma unroll
    for (int i = 0; i < 4; i++) {
        int row = by * 64 + r0 + i;
        int b = row >> 11, t = row & 2047;
        float* p = dst + (((size_t)(b * H_ + h) * T_ + t) * 64) + c0;
        p[0] = acc[i][0]; p[1] = acc[i][1]; p[2] = acc[i][2]; p[3] = acc[i][3];
    }
}

// ---------------- kernel 3: windowed dual flash-attention + headnorm ----------------
// grid (32 qtiles, 4 heads, 8 batch); 256 threads; dynamic smem ~84.5 KB
#define ATTN_SMEM_FLOATS (4160*2 + 4096 + 4160*2 + 6*64 + 8)

__global__ __launch_bounds__(256) void attn_kernel(
    const float* __restrict__ lq1, const float* __restrict__ lk1,
    const float* __restrict__ lq2, const float* __restrict__ lk2,
    const float* __restrict__ sig_s_p, const float* __restrict__ sig_n_p,
    const float* __restrict__ hn_w, const float* __restrict__ hn_b) {
    extern __shared__ float smf[];
    float* sQ  = smf;            // 64 x 65
    float* sK  = sQ  + 4160;     // 64 x 65
    float* sV  = sK  + 4160;     // 64 x 64 (unpadded, float4 reads)
    float* sS1 = sV  + 4096;     // 64 x 65
    float* sS2 = sS1 + 4160;     // 64 x 65
    float* sM1 = sS2 + 4160;
    float* sL1 = sM1 + 64;
    float* sM2 = sL1 + 64;
    float* sL2 = sM2 + 64;
    float* sR1 = sL2 + 64;
    float* sR2 = sR1 + 64;
    float* sLam = sR2 + 64;

    int qt = blockIdx.x, h = blockIdx.y, b = blockIdx.z;
    int qs = qt * 64;
    int tid = threadIdx.x;
    int ty = tid >> 4, tx = tid & 15;
    int r0 = ty * 4, c0 = tx * 4;

    const float* qbase = g_q + ((size_t)(b * H_ + h) * T_ + qs) * 64;
    const float* kbase = g_k + ((size_t)(b * H_ + h) * T_) * 64;
    const float* vbase = g_v + ((size_t)(b * H_ + h) * T_) * 64;

    // load Q tile (64x64) into padded smem
    #pragma unroll
    for (int u = 0; u < 4; u++) {
        int f = tid + u * 256;         // 0..1023
        int row = f >> 4, c4 = f & 15;
        float4 v = *(const float4*)(qbase + row * 64 + c4 * 4);
        sQ[row * 65 + c4 * 4 + 0] = v.x; sQ[row * 65 + c4 * 4 + 1] = v.y;
        sQ[row * 65 + c4 * 4 + 2] = v.z; sQ[row * 65 + c4 * 4 + 3] = v.w;
    }
    if (tid == 0) {
        float d1 = 0.f, d2 = 0.f;
        for (int i = 0; i < HD_; i++) { d1 += lq1[i] * lk1[i]; d2 += lq2[i] * lk2[i]; }
        *sLam = __expf(d1) - __expf(d2) + LAMBDA_INIT_;
    }
    if (tid < 64) { sM1[tid] = -1e30f; sL1[tid] = 0.f; sM2[tid] = -1e30f; sL2[tid] = 0.f; }

    float ss = fmaxf(sig_s_p[0], 1.f), sn = fmaxf(sig_n_p[0], 1.f);
    float inv2s = 0.5f / (ss * ss), inv2n = 0.5f / (sn * sn);
    float smax = fmaxf(ss, sn);
    int rcut = (int)(11.0f * smax) + 1;     // bias <= -60.5 beyond cut -> negligible
    int klo = qs - rcut;       if (klo < 0) klo = 0;
    int khi = qs + 63 + rcut;  if (khi > T_ - 1) khi = T_ - 1;
    int kt_lo = klo >> 6, kt_hi = khi >> 6;

    float o1[4][4] = {}, o2[4][4] = {};
    __syncthreads();

    for (int ktile = kt_lo; ktile <= kt_hi; ktile++) {
        int ks = ktile * 64;
        // load K (padded) and V (unpadded)
        #pragma unroll
        for (int u = 0; u < 4; u++) {
            int f = tid + u * 256;
            int row = f >> 4, c4 = f & 15;
            float4 kv = *(const float4*)(kbase + (size_t)(ks + row) * 64 + c4 * 4);
            sK[row * 65 + c4 * 4 + 0] = kv.x; sK[row * 65 + c4 * 4 + 1] = kv.y;
            sK[row * 65 + c4 * 4 + 2] = kv.z; sK[row * 65 + c4 * 4 + 3] = kv.w;
            float4 vv = *(const float4*)(vbase + (size_t)(ks + row) * 64 + c4 * 4);
            *(float4*)(sV + row * 64 + c4 * 4) = vv;
        }
        __syncthreads();

        // ---- S = Q K^T (two halves) ----
        float s1[4][4] = {}, s2[4][4] = {};
        #pragma unroll 8
        for (int d = 0; d < 32; d++) {
            float a0 = sQ[(r0+0)*65+d], a1 = sQ[(r0+1)*65+d], a2 = sQ[(r0+2)*65+d], a3 = sQ[(r0+3)*65+d];
            float k0 = sK[(c0+0)*65+d], k1 = sK[(c0+1)*65+d], k2 = sK[(c0+2)*65+d], k3 = sK[(c0+3)*65+d];
            s1[0][0]+=a0*k0; s1[0][1]+=a0*k1; s1[0][2]+=a0*k2; s1[0][3]+=a0*k3;
            s1[1][0]+=a1*k0; s1[1][1]+=a1*k1; s1[1][2]+=a1*k2; s1[1][3]+=a1*k3;
            s1[2][0]+=a2*k0; s1[2][1]+=a2*k1; s1[2][2]+=a2*k2; s1[2][3]+=a2*k3;
            s1[3][0]+=a3*k0; s1[3][1]+=a3*k1; s1[3][2]+=a3*k2; s1[3][3]+=a3*k3;
        }
        #pragma unroll 8
        for (int d = 32; d < 64; d++) {
            float a0 = sQ[(r0+0)*65+d], a1 = sQ[(r0+1)*65+d], a2 = sQ[(r0+2)*65+d], a3 = sQ[(r0+3)*65+d];
            float k0 = sK[(c0+0)*65+d], k1 = sK[(c0+1)*65+d], k2 = sK[(c0+2)*65+d], k3 = sK[(c0+3)*65+d];
            s2[0][0]+=a0*k0; s2[0][1]+=a0*k1; s2[0][2]+=a0*k2; s2[0][3]+=a0*k3;
            s2[1][0]+=a1*k0; s2[1][1]+=a1*k1; s2[1][2]+=a1*k2; s2[1][3]+=a1*k3;
            s2[2][0]+=a2*k0; s2[2][1]+=a2*k1; s2[2][2]+=a2*k2; s2[2][3]+=a2*k3;
            s2[3][0]+=a3*k0; s2[3][1]+=a3*k1; s2[3][2]+=a3*k2; s2[3][3]+=a3*k3;
        }
        #pragma unroll
        for (int i = 0; i < 4; i++) {
            #pragma unroll
            for (int j = 0; j < 4; j++) {
                float rel = (float)((ks + c0 + j) - (qs + r0 + i));
                float r2 = rel * rel;
                sS1[(r0+i)*65 + c0+j] = s1[i][j] * SCALE_ - inv2s * r2;
                sS2[(r0+i)*65 + c0+j] = s2[i][j] * SCALE_ - inv2n * r2;
            }
        }
        __syncthreads();

        // ---- online softmax update (128 workers: row r, set tid&1) ----
        if (tid < 128) {
            int r = tid >> 1;
            float* S = (tid & 1) ? sS2 : sS1;
            float* M = (tid & 1) ? sM2 : sM1;
            float* L = (tid & 1) ? sL2 : sL1;
            float* R = (tid & 1) ? sR2 : sR1;
            float mold = M[r];
            float mt = mold;
            #pragma unroll 8
            for (int k = 0; k < 64; k++) mt = fmaxf(mt, S[r*65 + k]);
            float resc = __expf(mold - mt);
            float l = L[r] * resc;
            #pragma unroll 8
            for (int k = 0; k < 64; k++) {
                float p = __expf(S[r*65 + k] - mt);
                S[r*65 + k] = p;
                l += p;
            }
            M[r] = mt; L[r] = l; R[r] = resc;
        }
        __syncthreads();

        // ---- PV accumulate (register O, rescale first) ----
        float rs1[4], rs2[4];
        #pragma unroll
        for (int i = 0; i < 4; i++) { rs1[i] = sR1[r0+i]; rs2[i] = sR2[r0+i]; }
        #pragma unroll
        for (int i = 0; i < 4; i++)
            #pragma unroll
            for (int j = 0; j < 4; j++) { o1[i][j] *= rs1[i]; o2[i][j] *= rs2[i]; }

        const float4* sV4 = (const float4*)sV;
        #pragma unroll 4
        for (int k = 0; k < 64; k++) {
            float4 vv = sV4[k * 16 + tx];
            #pragma unroll
            for (int i = 0; i < 4; i++) {
                float p1 = sS1[(r0+i)*65 + k];
                float p2 = sS2[(r0+i)*65 + k];
                o1[i][0] += p1 * vv.x; o1[i][1] += p1 * vv.y; o1[i][2] += p1 * vv.z; o1[i][3] += p1 * vv.w;
                o2[i][0] += p2 * vv.x; o2[i][1] += p2 * vv.y; o2[i][2] += p2 * vv.z; o2[i][3] += p2 * vv.w;
            }
        }
        __syncthreads();
    }

    // ---- epilogue: combine, headnorm, store ----
    float lam = *sLam;
    #pragma unroll
    for (int i = 0; i < 4; i++) {
        float il1 = 1.f / sL1[r0+i];
        float il2 = 1.f / sL2[r0+i];
        #pragma unroll
        for (int j = 0; j < 4; j++)
            sS1[(r0+i)*65 + c0+j] = o1[i][j] * il1 - lam * o2[i][j] * il2;
    }
    __syncthreads();
    if (tid < 64) {
        int r = tid;
        float mu = 0.f, sq = 0.f;
        #pragma unroll 8
        for (int j = 0; j < 64; j++) { float x = sS1[r*65 + j]; mu += x; sq += x * x; }
        mu *= (1.f / 64.f);
        float var = sq * (1.f / 64.f) - mu * mu;
        float rstd = rsqrtf(var + EPS_);
        float* dst = g_attn + (size_t)(b * T_ + qs + r) * 256 + h * 64;
        #pragma unroll 8
        for (int j = 0; j < 64; j++) {
            float x = sS1[r*65 + j];
            dst[j] = ((x - mu) * rstd * hn_w[j] + hn_b[j]) * (1.0f - LAMBDA_INIT_);
        }
    }
}

// ---------------- kernel 4: output GEMM + residual ----------------
// out[16384 x 128] = g_attn[16384 x 256] @ wo[256 x 128] + tokens
__global__ __launch_bounds__(256) void out_gemm_kernel(const float* __restrict__ wo,
                                                       const float* __restrict__ tokens,
                                                       float* __restrict__ out) {
    __shared__ float sA[64][33];
    __shared__ float sB[32][64];
    int bx = blockIdx.x;        // 0..1
    int by = blockIdx.y;        // 0..255
    int tid = threadIdx.x;
    int ty = tid >> 4, tx = tid & 15;
    int r0 = ty * 4, c0 = tx * 4;
    float acc[4][4] = {};
    const float* Ab = g_attn + (size_t)(by * 64) * 256;

    for (int kt = 0; kt < 8; kt++) {
        #pragma unroll
        for (int u = 0; u < 2; u++) {
            int f = tid + u * 256;
            int row = f >> 3, c4 = f & 7;
            float4 v = *(const float4*)(Ab + (size_t)row * 256 + kt * 32 + c4 * 4);
            sA[row][c4 * 4 + 0] = v.x; sA[row][c4 * 4 + 1] = v.y;
            sA[row][c4 * 4 + 2] = v.z; sA[row][c4 * 4 + 3] = v.w;
        }
        #pragma unroll
        for (int u = 0; u < 2; u++) {
            int f = tid + u * 256;
            int kr = f >> 4, c4 = f & 15;
            *(float4*)(&sB[kr][c4 * 4]) =
                *(const float4*)(wo + (size_t)(kt * 32 + kr) * 128 + bx * 64 + c4 * 4);
        }
        __syncthreads();
        #pragma unroll 8
        for (int kk = 0; kk < 32; kk++) {
            float a0 = sA[r0 + 0][kk], a1 = sA[r0 + 1][kk];
            float a2 = sA[r0 + 2][kk], a3 = sA[r0 + 3][kk];
            float4 bvv = *(const float4*)(&sB[kk][c0]);
            acc[0][0] += a0 * bvv.x; acc[0][1] += a0 * bvv.y; acc[0][2] += a0 * bvv.z; acc[0][3] += a0 * bvv.w;
            acc[1][0] += a1 * bvv.x; acc[1][1] += a1 * bvv.y; acc[1][2] += a1 * bvv.z; acc[1][3] += a1 * bvv.w;
            acc[2][0] += a2 * bvv.x; acc[2][1] += a2 * bvv.y; acc[2][2] += a2 * bvv.z; acc[2][3] += a2 * bvv.w;
            acc[3][0] += a3 * bvv.x; acc[3][1] += a3 * bvv.y; acc[3][2] += a3 * bvv.z; acc[3][3] += a3 * bvv.w;
        }
        __syncthreads();
    }
    #pragma unroll
    for (int i = 0; i < 4; i++) {
        int row = by * 64 + r0 + i;
        #pragma unroll
        for (int j = 0; j < 4; j++) {
            int col = bx * 64 + c0 + j;
            out[(size_t)row * 128 + col] = acc[i][j] + tokens[(size_t)row * 128 + col];
        }
    }
}

// ---------------- launch ----------------
extern "C" void kernel_launch(void* const* d_in, const int* in_sizes, int n_in,
                              void* d_out, int out_size) {
    const float* tokens = (const float*)d_in[0];
    const float* ln_w   = (const float*)d_in[1];
    const float* ln_b   = (const float*)d_in[2];
    const float* wq     = (const float*)d_in[3];
    const float* wk     = (const float*)d_in[4];
    const float* wv     = (const float*)d_in[5];
    const float* wo     = (const float*)d_in[6];
    const float* lq1    = (const float*)d_in[7];
    const float* lk1    = (const float*)d_in[8];
    const float* lq2    = (const float*)d_in[9];
    const float* lk2    = (const float*)d_in[10];
    const float* sigs   = (const float*)d_in[11];
    const float* sign   = (const float*)d_in[12];
    const float* hnw    = (const float*)d_in[13];
    const float* hnb    = (const float*)d_in[14];
    float* out = (float*)d_out;

    ln_kernel<<<NTOK / 8, 256>>>(tokens, ln_w, ln_b);
    qkv_gemm_kernel<<<dim3(12, 256), 256>>>(wq, wk, wv);

    int attn_smem = ATTN_SMEM_FLOATS * (int)sizeof(float);
    cudaFuncSetAttribute(attn_kernel, cudaFuncAttributeMaxDynamicSharedMemorySize, attn_smem);
    attn_kernel<<<dim3(32, H_, B_), 256, attn_smem>>>(lq1, lk1, lq2, lk2, sigs, sign, hnw, hnb);

    out_gemm_kernel<<<dim3(2, 256), 256>>>(wo, tokens, out);
}

// round 8
// speedup vs baseline: 1.1187x; 1.1187x over previous
#include <cuda_runtime.h>
#include <math.h>
#include <stdint.h>
#include <mma.h>
using namespace nvcuda;

#define B_ 8
#define T_ 2048
#define D_ 128
#define H_ 4
#define HD_ 32
#define NTOK (B_*T_)
#define SCALE_ 0.17677669529663687f
#define EPS_ 1e-5f
#define LAMBDA_INIT_ 0.8f

// ---------------- scratch ----------------
__device__ float g_xln[NTOK * D_];
__device__ float g_q[B_ * H_ * T_ * 64];
__device__ float g_k[B_ * H_ * T_ * 64];
__device__ float g_v[B_ * H_ * T_ * 64];
__device__ float g_attn[NTOK * 256];

// ---------------- kernel 1: LayerNorm ----------------
__global__ __launch_bounds__(256) void ln_kernel(const float* __restrict__ tokens,
                                                 const float* __restrict__ w,
                                                 const float* __restrict__ b) {
    int warp = threadIdx.x >> 5, lane = threadIdx.x & 31;
    int t = blockIdx.x * 8 + warp;
    const float4* src = (const float4*)(tokens + (size_t)t * 128);
    float4 x = src[lane];
    float s = x.x + x.y + x.z + x.w;
    float q = x.x * x.x + x.y * x.y + x.z * x.z + x.w * x.w;
    #pragma unroll
    for (int o = 16; o; o >>= 1) {
        s += __shfl_xor_sync(0xFFFFFFFFu, s, o);
        q += __shfl_xor_sync(0xFFFFFFFFu, q, o);
    }
    float mu = s * (1.f / 128.f);
    float var = q * (1.f / 128.f) - mu * mu;
    float rstd = rsqrtf(var + EPS_);
    float4 wv = ((const float4*)w)[lane];
    float4 bv = ((const float4*)b)[lane];
    float4 y;
    y.x = (x.x - mu) * rstd * wv.x + bv.x;
    y.y = (x.y - mu) * rstd * wv.y + bv.y;
    y.z = (x.z - mu) * rstd * wv.z + bv.z;
    y.w = (x.w - mu) * rstd * wv.w + bv.w;
    ((float4*)g_xln)[(size_t)t * 32 + lane] = y;
}

// ---------------- kernel 2: QKV projection via wmma tf32 ----------------
// grid (6, 128): bx = 128-col chunk of [wq|wk|wv] (768 cols), by = 128-token block.
// 8 warps; warp tile 64x32 = 4x2 wmma(16x16x8) frags. X tile in smem, W from global.
#define QKV_SMEM_BYTES (128 * 136 * 4)

__global__ __launch_bounds__(256) void qkv_wmma_kernel(const float* __restrict__ wq,
                                                       const float* __restrict__ wk,
                                                       const float* __restrict__ wv) {
    extern __shared__ float sX[];   // [128][136]
    int tid = threadIdx.x, wid = tid >> 5;
    int bx = blockIdx.x, by = blockIdx.y;

    // stage X tile [128 tok x 128 k]
    const float* Xb = g_xln + (size_t)by * 128 * 128;
    #pragma unroll
    for (int it = 0; it < 16; it++) {
        int f = tid + it * 256;           // 0..4095 float4s
        int row = f >> 5, c4 = f & 31;
        float4 v = *(const float4*)(Xb + row * 128 + c4 * 4);
        *(float4*)(&sX[row * 136 + c4 * 4]) = v;
    }
    __syncthreads();

    int wr = wid >> 2, wc = wid & 3;      // warp 64-row half, 32-col quarter
    int mat = bx >> 1;
    const float* W = (mat == 0) ? wq : (mat == 1 ? wk : wv);
    int ncol0 = (bx & 1) * 128;

    wmma::fragment<wmma::accumulator, 16, 16, 8, float> acc[4][2];
    #pragma unroll
    for (int i = 0; i < 4; i++)
        #pragma unroll
        for (int j = 0; j < 2; j++) wmma::fill_fragment(acc[i][j], 0.0f);

    for (int kt = 0; kt < 16; kt++) {
        wmma::fragment<wmma::matrix_a, 16, 16, 8, wmma::precision::tf32, wmma::row_major> a[4];
        #pragma unroll
        for (int i = 0; i < 4; i++) {
            wmma::load_matrix_sync(a[i], &sX[(wr * 64 + i * 16) * 136 + kt * 8], 136);
            #pragma unroll
            for (int e = 0; e < a[i].num_elements; e++) a[i].x[e] = wmma::__float_to_tf32(a[i].x[e]);
        }
        wmma::fragment<wmma::matrix_b, 16, 16, 8, wmma::precision::tf32, wmma::row_major> bfr[2];
        #pragma unroll
        for (int j = 0; j < 2; j++) {
            wmma::load_matrix_sync(bfr[j], W + (size_t)(kt * 8) * 256 + ncol0 + wc * 32 + j * 16, 256);
            #pragma unroll
            for (int e = 0; e < bfr[j].num_elements; e++) bfr[j].x[e] = wmma::__float_to_tf32(bfr[j].x[e]);
        }
        #pragma unroll
        for (int i = 0; i < 4; i++)
            #pragma unroll
            for (int j = 0; j < 2; j++) wmma::mma_sync(acc[i][j], a[i], bfr[j], acc[i][j]);
    }

    // direct store: each 16-col frag lies within one head's 64-dim chunk
    int b_ = by >> 4;                       // batch (16 blocks of 128 per batch)
    #pragma unroll
    for (int i = 0; i < 4; i++) {
        int t0 = (by * 128 + wr * 64 + i * 16) & 2047;
        #pragma unroll
        for (int j = 0; j < 2; j++) {
            int gc = bx * 128 + wc * 32 + j * 16;   // global col 0..767
            int m2 = gc >> 8;                        // 0=q,1=k,2=v
            int cc = gc & 255;
            int h = cc >> 6, d = cc & 63;
            float* dst = (m2 == 0 ? g_q : (m2 == 1 ? g_k : g_v)) +
                         (((size_t)(b_ * 4 + h) * 2048 + t0) * 64 + d);
            wmma::store_matrix_sync(dst, acc[i][j], 64, wmma::mem_row_major);
        }
    }
}

// ---------------- kernel 4: output GEMM via wmma tf32, residual fused ----------------
// out[16384x128] = g_attn[16384x256] @ wo[256x128] + tokens. grid 128, 8 warps.
__global__ __launch_bounds__(256) void out_wmma_kernel(const float* __restrict__ wo,
                                                       const float* __restrict__ tokens,
                                                       float* __restrict__ out) {
    int tid = threadIdx.x, wid = tid >> 5;
    int blk = blockIdx.x;
    int wr = wid >> 2, wc = wid & 3;

    wmma::fragment<wmma::accumulator, 16, 16, 8, float> acc[4][2];
    #pragma unroll
    for (int i = 0; i < 4; i++)
        #pragma unroll
        for (int j = 0; j < 2; j++)
            wmma::load_matrix_sync(acc[i][j],
                tokens + (size_t)(blk * 128 + wr * 64 + i * 16) * 128 + wc * 32 + j * 16,
                128, wmma::mem_row_major);

    for (int kt = 0; kt < 32; kt++) {
        wmma::fragment<wmma::matrix_a, 16, 16, 8, wmma::precision::tf32, wmma::row_major> a[4];
        #pragma unroll
        for (int i = 0; i < 4; i++) {
            wmma::load_matrix_sync(a[i],
                g_attn + (size_t)(blk * 128 + wr * 64 + i * 16) * 256 + kt * 8, 256);
            #pragma unroll
            for (int e = 0; e < a[i].num_elements; e++) a[i].x[e] = wmma::__float_to_tf32(a[i].x[e]);
        }
        wmma::fragment<wmma::matrix_b, 16, 16, 8, wmma::precision::tf32, wmma::row_major> bfr[2];
        #pragma unroll
        for (int j = 0; j < 2; j++) {
            wmma::load_matrix_sync(bfr[j], wo + (size_t)(kt * 8) * 128 + wc * 32 + j * 16, 128);
            #pragma unroll
            for (int e = 0; e < bfr[j].num_elements; e++) bfr[j].x[e] = wmma::__float_to_tf32(bfr[j].x[e]);
        }
        #pragma unroll
        for (int i = 0; i < 4; i++)
            #pragma unroll
            for (int j = 0; j < 2; j++) wmma::mma_sync(acc[i][j], a[i], bfr[j], acc[i][j]);
    }

    #pragma unroll
    for (int i = 0; i < 4; i++)
        #pragma unroll
        for (int j = 0; j < 2; j++)
            wmma::store_matrix_sync(
                out + (size_t)(blk * 128 + wr * 64 + i * 16) * 128 + wc * 32 + j * 16,
                acc[i][j], 128, wmma::mem_row_major);
}

// ---------------- kernel 3: windowed dual flash-attention + headnorm (unchanged) ----------------
#define ATTN_SMEM_FLOATS (4160*2 + 4096 + 4160*2 + 6*64 + 8)

__global__ __launch_bounds__(256) void attn_kernel(
    const float* __restrict__ lq1, const float* __restrict__ lk1,
    const float* __restrict__ lq2, const float* __restrict__ lk2,
    const float* __restrict__ sig_s_p, const float* __restrict__ sig_n_p,
    const float* __restrict__ hn_w, const float* __restrict__ hn_b) {
    extern __shared__ float smf[];
    float* sQ  = smf;
    float* sK  = sQ  + 4160;
    float* sV  = sK  + 4160;
    float* sS1 = sV  + 4096;
    float* sS2 = sS1 + 4160;
    float* sM1 = sS2 + 4160;
    float* sL1 = sM1 + 64;
    float* sM2 = sL1 + 64;
    float* sL2 = sM2 + 64;
    float* sR1 = sL2 + 64;
    float* sR2 = sR1 + 64;
    float* sLam = sR2 + 64;

    int qt = blockIdx.x, h = blockIdx.y, b = blockIdx.z;
    int qs = qt * 64;
    int tid = threadIdx.x;
    int ty = tid >> 4, tx = tid & 15;
    int r0 = ty * 4, c0 = tx * 4;

    const float* qbase = g_q + ((size_t)(b * H_ + h) * T_ + qs) * 64;
    const float* kbase = g_k + ((size_t)(b * H_ + h) * T_) * 64;
    const float* vbase = g_v + ((size_t)(b * H_ + h) * T_) * 64;

    #pragma unroll
    for (int u = 0; u < 4; u++) {
        int f = tid + u * 256;
        int row = f >> 4, c4 = f & 15;
        float4 v = *(const float4*)(qbase + row * 64 + c4 * 4);
        sQ[row * 65 + c4 * 4 + 0] = v.x; sQ[row * 65 + c4 * 4 + 1] = v.y;
        sQ[row * 65 + c4 * 4 + 2] = v.z; sQ[row * 65 + c4 * 4 + 3] = v.w;
    }
    if (tid == 0) {
        float d1 = 0.f, d2 = 0.f;
        for (int i = 0; i < HD_; i++) { d1 += lq1[i] * lk1[i]; d2 += lq2[i] * lk2[i]; }
        *sLam = __expf(d1) - __expf(d2) + LAMBDA_INIT_;
    }
    if (tid < 64) { sM1[tid] = -1e30f; sL1[tid] = 0.f; sM2[tid] = -1e30f; sL2[tid] = 0.f; }

    float ss = fmaxf(sig_s_p[0], 1.f), sn = fmaxf(sig_n_p[0], 1.f);
    float inv2s = 0.5f / (ss * ss), inv2n = 0.5f / (sn * sn);
    float smax = fmaxf(ss, sn);
    int rcut = (int)(11.0f * smax) + 1;
    int klo = qs - rcut;       if (klo < 0) klo = 0;
    int khi = qs + 63 + rcut;  if (khi > T_ - 1) khi = T_ - 1;
    int kt_lo = klo >> 6, kt_hi = khi >> 6;

    float o1[4][4] = {}, o2[4][4] = {};
    __syncthreads();

    for (int ktile = kt_lo; ktile <= kt_hi; ktile++) {
        int ks = ktile * 64;
        #pragma unroll
        for (int u = 0; u < 4; u++) {
            int f = tid + u * 256;
            int row = f >> 4, c4 = f & 15;
            float4 kv = *(const float4*)(kbase + (size_t)(ks + row) * 64 + c4 * 4);
            sK[row * 65 + c4 * 4 + 0] = kv.x; sK[row * 65 + c4 * 4 + 1] = kv.y;
            sK[row * 65 + c4 * 4 + 2] = kv.z; sK[row * 65 + c4 * 4 + 3] = kv.w;
            float4 vv = *(const float4*)(vbase + (size_t)(ks + row) * 64 + c4 * 4);
            *(float4*)(sV + row * 64 + c4 * 4) = vv;
        }
        __syncthreads();

        float s1[4][4] = {}, s2[4][4] = {};
        #pragma unroll 8
        for (int d = 0; d < 32; d++) {
            float a0 = sQ[(r0+0)*65+d], a1 = sQ[(r0+1)*65+d], a2 = sQ[(r0+2)*65+d], a3 = sQ[(r0+3)*65+d];
            float k0 = sK[(c0+0)*65+d], k1 = sK[(c0+1)*65+d], k2 = sK[(c0+2)*65+d], k3 = sK[(c0+3)*65+d];
            s1[0][0]+=a0*k0; s1[0][1]+=a0*k1; s1[0][2]+=a0*k2; s1[0][3]+=a0*k3;
            s1[1][0]+=a1*k0; s1[1][1]+=a1*k1; s1[1][2]+=a1*k2; s1[1][3]+=a1*k3;
            s1[2][0]+=a2*k0; s1[2][1]+=a2*k1; s1[2][2]+=a2*k2; s1[2][3]+=a2*k3;
            s1[3][0]+=a3*k0; s1[3][1]+=a3*k1; s1[3][2]+=a3*k2; s1[3][3]+=a3*k3;
        }
        #pragma unroll 8
        for (int d = 32; d < 64; d++) {
            float a0 = sQ[(r0+0)*65+d], a1 = sQ[(r0+1)*65+d], a2 = sQ[(r0+2)*65+d], a3 = sQ[(r0+3)*65+d];
            float k0 = sK[(c0+0)*65+d], k1 = sK[(c0+1)*65+d], k2 = sK[(c0+2)*65+d], k3 = sK[(c0+3)*65+d];
            s2[0][0]+=a0*k0; s2[0][1]+=a0*k1; s2[0][2]+=a0*k2; s2[0][3]+=a0*k3;
            s2[1][0]+=a1*k0; s2[1][1]+=a1*k1; s2[1][2]+=a1*k2; s2[1][3]+=a1*k3;
            s2[2][0]+=a2*k0; s2[2][1]+=a2*k1; s2[2][2]+=a2*k2; s2[2][3]+=a2*k3;
            s2[3][0]+=a3*k0; s2[3][1]+=a3*k1; s2[3][2]+=a3*k2; s2[3][3]+=a3*k3;
        }
        #pragma unroll
        for (int i = 0; i < 4; i++) {
            #pragma unroll
            for (int j = 0; j < 4; j++) {
                float rel = (float)((ks + c0 + j) - (qs + r0 + i));
                float r2 = rel * rel;
                sS1[(r0+i)*65 + c0+j] = s1[i][j] * SCALE_ - inv2s * r2;
                sS2[(r0+i)*65 + c0+j] = s2[i][j] * SCALE_ - inv2n * r2;
            }
        }
        __syncthreads();

        if (tid < 128) {
            int r = tid >> 1;
            float* S = (tid & 1) ? sS2 : sS1;
            float* M = (tid & 1) ? sM2 : sM1;
            float* L = (tid & 1) ? sL2 : sL1;
            float* R = (tid & 1) ? sR2 : sR1;
            float mold = M[r];
            float mt = mold;
            #pragma unroll 8
            for (int k = 0; k < 64; k++) mt = fmaxf(mt, S[r*65 + k]);
            float resc = __expf(mold - mt);
            float l = L[r] * resc;
            #pragma unroll 8
            for (int k = 0; k < 64; k++) {
                float p = __expf(S[r*65 + k] - mt);
                S[r*65 + k] = p;
                l += p;
            }
            M[r] = mt; L[r] = l; R[r] = resc;
        }
        __syncthreads();

        float rs1[4], rs2[4];
        #pragma unroll
        for (int i = 0; i < 4; i++) { rs1[i] = sR1[r0+i]; rs2[i] = sR2[r0+i]; }
        #pragma unroll
        for (int i = 0; i < 4; i++)
            #pragma unroll
            for (int j = 0; j < 4; j++) { o1[i][j] *= rs1[i]; o2[i][j] *= rs2[i]; }

        const float4* sV4 = (const float4*)sV;
        #pragma unroll 4
        for (int k = 0; k < 64; k++) {
            float4 vv = sV4[k * 16 + tx];
            #pragma unroll
            for (int i = 0; i < 4; i++) {
                float p1 = sS1[(r0+i)*65 + k];
                float p2 = sS2[(r0+i)*65 + k];
                o1[i][0] += p1 * vv.x; o1[i][1] += p1 * vv.y; o1[i][2] += p1 * vv.z; o1[i][3] += p1 * vv.w;
                o2[i][0] += p2 * vv.x; o2[i][1] += p2 * vv.y; o2[i][2] += p2 * vv.z; o2[i][3] += p2 * vv.w;
            }
        }
        __syncthreads();
    }

    float lam = *sLam;
    #pragma unroll
    for (int i = 0; i < 4; i++) {
        float il1 = 1.f / sL1[r0+i];
        float il2 = 1.f / sL2[r0+i];
        #pragma unroll
        for (int j = 0; j < 4; j++)
            sS1[(r0+i)*65 + c0+j] = o1[i][j] * il1 - lam * o2[i][j] * il2;
    }
    __syncthreads();
    if (tid < 64) {
        int r = tid;
        float mu = 0.f, sq = 0.f;
        #pragma unroll 8
        for (int j = 0; j < 64; j++) { float x = sS1[r*65 + j]; mu += x; sq += x * x; }
        mu *= (1.f / 64.f);
        float var = sq * (1.f / 64.f) - mu * mu;
        float rstd = rsqrtf(var + EPS_);
        float* dst = g_attn + (size_t)(b * T_ + qs + r) * 256 + h * 64;
        #pragma unroll 8
        for (int j = 0; j < 64; j++) {
            float x = sS1[r*65 + j];
            dst[j] = ((x - mu) * rstd * hn_w[j] + hn_b[j]) * (1.0f - LAMBDA_INIT_);
        }
    }
}

// ---------------- launch ----------------
extern "C" void kernel_launch(void* const* d_in, const int* in_sizes, int n_in,
                              void* d_out, int out_size) {
    const float* tokens = (const float*)d_in[0];
    const float* ln_w   = (const float*)d_in[1];
    const float* ln_b   = (const float*)d_in[2];
    const float* wq     = (const float*)d_in[3];
    const float* wk     = (const float*)d_in[4];
    const float* wv     = (const float*)d_in[5];
    const float* wo     = (const float*)d_in[6];
    const float* lq1    = (const float*)d_in[7];
    const float* lk1    = (const float*)d_in[8];
    const float* lq2    = (const float*)d_in[9];
    const float* lk2    = (const float*)d_in[10];
    const float* sigs   = (const float*)d_in[11];
    const float* sign   = (const float*)d_in[12];
    const float* hnw    = (const float*)d_in[13];
    const float* hnb    = (const float*)d_in[14];
    float* out = (float*)d_out;

    ln_kernel<<<NTOK / 8, 256>>>(tokens, ln_w, ln_b);

    cudaFuncSetAttribute(qkv_wmma_kernel, cudaFuncAttributeMaxDynamicSharedMemorySize, QKV_SMEM_BYTES);
    qkv_wmma_kernel<<<dim3(6, 128), 256, QKV_SMEM_BYTES>>>(wq, wk, wv);

    int attn_smem = ATTN_SMEM_FLOATS * (int)sizeof(float);
    cudaFuncSetAttribute(attn_kernel, cudaFuncAttributeMaxDynamicSharedMemorySize, attn_smem);
    attn_kernel<<<dim3(32, H_, B_), 256, attn_smem>>>(lq1, lk1, lq2, lk2, sigs, sign, hnw, hnb);

    out_wmma_kernel<<<128, 256>>>(wo, tokens, out);
}